// round 9
// baseline (speedup 1.0000x reference)
#include <cuda_runtime.h>
#include <cstdint>
#include <math.h>

// ---------------- problem constants ----------------
#define NROWS   65536
#define SDIM    256
#define ADIM    129
#define HID     256
#define NSTEP   30
#define EPS_LN  1e-5f

#define TM      32      // rows per CTA
#define RPW     8       // rows per warp (4 warps * 8 = 32)
#define XSTR    132     // padded float stride for x rows

typedef unsigned long long u64;

// packed fp32x2 helpers (sm_103a FFMA2)
__device__ __forceinline__ u64 pk2(float lo, float hi) {
    u64 r; asm("mov.b64 %0,{%1,%2};" : "=l"(r) : "f"(lo), "f"(hi)); return r;
}
__device__ __forceinline__ float2 up2(u64 v) {
    float lo, hi; asm("mov.b64 {%0,%1},%2;" : "=f"(lo), "=f"(hi) : "l"(v));
    float2 f; f.x = lo; f.y = hi; return f;
}
__device__ __forceinline__ void fma2(u64 &d, u64 a, u64 b) {
    asm("fma.rn.f32x2 %0,%1,%2,%0;" : "+l"(d) : "l"(a), "l"(b));
}

// W1 x-part (rows 256..384) zero-padded to 132 k-rows, stride 256
__device__ float g_W1xp[132 * HID];
// W3 zero-padded to 132 cols, stride 132
__device__ float g_W3p[HID * 132];
// S1 = state @ W1[0:256,:] + b1, spilled to global (64 MB, L2-resident).
// Written and read by the SAME thread -> no synchronization needed.
__device__ float g_S1[(size_t)NROWS * HID];

__global__ void pack_kernel(const float* __restrict__ W1, const float* __restrict__ W3) {
    int i = blockIdx.x * blockDim.x + threadIdx.x;
    if (i < 132 * HID) {
        int k = i / HID, c = i - k * HID;
        g_W1xp[i] = (k < 129) ? W1[(size_t)(SDIM + k) * HID + c] : 0.0f;
    }
    if (i < HID * 132) {
        int k = i / 132, c = i - k * 132;
        g_W3p[i] = (c < ADIM) ? W3[k * ADIM + c] : 0.0f;
    }
}

// ---- weights: one 2-k block (256-wide rows) as u64 halves (8 regs-pairs) ----
__device__ __forceinline__ void loadw2(u64 w[8], const float* __restrict__ Wg,
                                       int jb2, int c0, int c1) {
    #pragma unroll
    for (int j = 0; j < 2; j++) {
        const float* p = Wg + (size_t)(jb2 * 2 + j) * HID;
        const ulonglong2 a = *(const ulonglong2*)(p + c0);
        const ulonglong2 b = *(const ulonglong2*)(p + c1);
        w[4*j+0] = a.x; w[4*j+1] = a.y; w[4*j+2] = b.x; w[4*j+3] = b.y;
    }
}

// ---- activations: one 2-k block for 8 rows (broadcast LDS.64) ----
__device__ __forceinline__ void loada2(float2 av[RPW], const float* __restrict__ src,
                                       int sstr, int jb2) {
    #pragma unroll
    for (int i = 0; i < RPW; i++)
        av[i] = *(const float2*)(src + i * sstr + jb2 * 2);
}

// ---- FMA one 2-k block ----
__device__ __forceinline__ void fmab2(const u64 w[8], const float2 av[RPW],
                                      u64 acc[RPW][4]) {
    #pragma unroll
    for (int j = 0; j < 2; j++) {
        #pragma unroll
        for (int i = 0; i < RPW; i++) {
            const float v = j ? av[i].y : av[i].x;
            const u64 xv = pk2(v, v);
            fma2(acc[i][0], w[4*j+0], xv);
            fma2(acc[i][1], w[4*j+1], xv);
            fma2(acc[i][2], w[4*j+2], xv);
            fma2(acc[i][3], w[4*j+3], xv);
        }
    }
}

// ---- GEMM over K2 2-k blocks, ping-pong prefetch of weights AND acts ----
template<int K2>   // K2 must be even
__device__ __forceinline__ void gemm2(const float* __restrict__ Wg,
                                      const float* __restrict__ src, int sstr,
                                      u64 acc[RPW][4], int c0, int c1)
{
    u64 wA[8], wB[8];
    float2 aA[RPW], aB[RPW];
    loadw2(wA, Wg, 0, c0, c1);
    loada2(aA, src, sstr, 0);
    #pragma unroll 1
    for (int jb = 0; jb < K2 - 1; jb += 2) {
        loadw2(wB, Wg, jb + 1, c0, c1);
        loada2(aB, src, sstr, jb + 1);
        fmab2(wA, aA, acc);
        if (jb + 2 < K2) {
            loadw2(wA, Wg, jb + 2, c0, c1);
            loada2(aA, src, sstr, jb + 2);
        }
        fmab2(wB, aB, acc);
    }
}

// ---- layer-3 variant: 4 cols/lane, weights g_W3p (stride 132) ----
__device__ __forceinline__ void loadw32(u64 w[4], int jb2, int c0) {
    #pragma unroll
    for (int j = 0; j < 2; j++) {
        const ulonglong2 a =
            *(const ulonglong2*)(g_W3p + (size_t)(jb2 * 2 + j) * 132 + c0);
        w[2*j] = a.x; w[2*j+1] = a.y;
    }
}
__device__ __forceinline__ void fmab32(const u64 w[4], const float2 av[RPW],
                                       u64 acc[RPW][2]) {
    #pragma unroll
    for (int j = 0; j < 2; j++) {
        #pragma unroll
        for (int i = 0; i < RPW; i++) {
            const float v = j ? av[i].y : av[i].x;
            const u64 xv = pk2(v, v);
            fma2(acc[i][0], w[2*j],   xv);
            fma2(acc[i][1], w[2*j+1], xv);
        }
    }
}

// LayerNorm (two-pass) + ReLU + store to smem (stride 256)
__device__ __forceinline__ void ln_relu_store(u64 acc[RPW][4], float* __restrict__ dst,
                                              const float* __restrict__ g,
                                              const float* __restrict__ be,
                                              int c0, int c1)
{
    const float4 ga = *(const float4*)(g + c0);
    const float4 gb = *(const float4*)(g + c1);
    const float4 ba = *(const float4*)(be + c0);
    const float4 bb = *(const float4*)(be + c1);
    #pragma unroll
    for (int i = 0; i < RPW; i++) {
        float2 a0 = up2(acc[i][0]), a1 = up2(acc[i][1]);
        float2 a2 = up2(acc[i][2]), a3 = up2(acc[i][3]);
        float s = ((a0.x + a0.y) + (a1.x + a1.y)) + ((a2.x + a2.y) + (a3.x + a3.y));
        #pragma unroll
        for (int o = 16; o > 0; o >>= 1) s += __shfl_xor_sync(0xffffffffu, s, o);
        const float m = s * (1.0f / 256.0f);
        const float d0 = a0.x - m, d1 = a0.y - m, d2 = a1.x - m, d3 = a1.y - m;
        const float d4 = a2.x - m, d5 = a2.y - m, d6 = a3.x - m, d7 = a3.y - m;
        float ss = ((d0*d0 + d1*d1) + (d2*d2 + d3*d3)) + ((d4*d4 + d5*d5) + (d6*d6 + d7*d7));
        #pragma unroll
        for (int o = 16; o > 0; o >>= 1) ss += __shfl_xor_sync(0xffffffffu, ss, o);
        const float inv = rsqrtf(ss * (1.0f / 256.0f) + EPS_LN);
        float4 h0, h1;
        h0.x = fmaxf(d0 * inv * ga.x + ba.x, 0.0f);
        h0.y = fmaxf(d1 * inv * ga.y + ba.y, 0.0f);
        h0.z = fmaxf(d2 * inv * ga.z + ba.z, 0.0f);
        h0.w = fmaxf(d3 * inv * ga.w + ba.w, 0.0f);
        h1.x = fmaxf(d4 * inv * gb.x + bb.x, 0.0f);
        h1.y = fmaxf(d5 * inv * gb.y + bb.y, 0.0f);
        h1.z = fmaxf(d6 * inv * gb.z + bb.z, 0.0f);
        h1.w = fmaxf(d7 * inv * gb.w + bb.w, 0.0f);
        *(float4*)(dst + i * HID + c0) = h0;
        *(float4*)(dst + i * HID + c1) = h1;
    }
}

// smem per CTA: h [32][256] + x [32][132] = 49664 B -> 3 CTAs/SM (145.5 KB)
#define HBF   (TM * HID)
#define XSF   (TM * XSTR)
#define SMEM_BYTES ((HBF + XSF) * sizeof(float))

__global__ void __launch_bounds__(128, 3)
actor_kernel(const float* __restrict__ state,  const float* __restrict__ amask,
             const float* __restrict__ x_init, const float* __restrict__ gumbel,
             const float* __restrict__ W1,     const float* __restrict__ b1,
             const float* __restrict__ g1,     const float* __restrict__ be1,
             const float* __restrict__ W2,     const float* __restrict__ b2,
             const float* __restrict__ g2,     const float* __restrict__ be2,
             const float* __restrict__ b3,     float* __restrict__ out)
{
    extern __shared__ float sm[];
    float* hb = sm;                    // [TM][256] h buffer
    float* xs = sm + HBF;              // [TM][132] x (129 live + zero pad)

    const int lane  = threadIdx.x & 31;
    const int wid   = threadIdx.x >> 5;
    const int rbase = wid * RPW;
    const size_t grow0 = (size_t)blockIdx.x * TM;
    const int c0 = lane * 4;
    const int c1 = 128 + lane * 4;

    float* xw = xs + rbase * XSTR;
    float* hw = hb + rbase * HID;
    float* s1w = g_S1 + (grow0 + rbase) * HID;   // global, thread-private access

    // ---- load x rows (stride 129, scalar coalesced) + zero pads ----
    #pragma unroll
    for (int i = 0; i < RPW; i++) {
        const size_t gr = grow0 + rbase + i;
        const float* xp = x_init + gr * ADIM;
        #pragma unroll
        for (int j = 0; j < 4; j++) xw[i * XSTR + lane + 32 * j] = xp[lane + 32 * j];
        if (lane == 0) xw[i * XSTR + 128] = xp[128];
        if (lane >= 1 && lane <= 3) xw[i * XSTR + 128 + lane] = 0.0f;
    }
    // ---- stage state rows in hb ----
    #pragma unroll
    for (int i = 0; i < RPW; i++) {
        const float* sp = state + (grow0 + rbase + i) * SDIM;
        *(float4*)(hw + i * HID + c0) = *(const float4*)(sp + c0);
        *(float4*)(hw + i * HID + c1) = *(const float4*)(sp + c1);
    }
    __syncwarp();

    // step-invariant preloads
    float w128[8];  // W3 col 128, lane-strided over k
    #pragma unroll
    for (int j = 0; j < 8; j++) w128[j] = g_W3p[(size_t)(lane + 32 * j) * 132 + 128];
    const float b3L = __ldg(b3 + 128);

    u64 acc[RPW][4];

    // ---- S1 = state @ W1[0:256,:] + b1 (hoisted), spill to g_S1 ----
    {
        const float4 ba = *(const float4*)(b1 + c0);
        const float4 bb = *(const float4*)(b1 + c1);
        #pragma unroll
        for (int i = 0; i < RPW; i++) {
            acc[i][0] = pk2(ba.x, ba.y); acc[i][1] = pk2(ba.z, ba.w);
            acc[i][2] = pk2(bb.x, bb.y); acc[i][3] = pk2(bb.z, bb.w);
        }
        gemm2<128>(W1, hw, HID, acc, c0, c1);
        #pragma unroll
        for (int i = 0; i < RPW; i++) {
            float2 a0 = up2(acc[i][0]), a1 = up2(acc[i][1]);
            float2 a2 = up2(acc[i][2]), a3 = up2(acc[i][3]);
            float4 v0; v0.x = a0.x; v0.y = a0.y; v0.z = a1.x; v0.w = a1.y;
            float4 v1; v1.x = a2.x; v1.y = a2.y; v1.z = a3.x; v1.w = a3.y;
            *(float4*)(s1w + i * HID + c0) = v0;
            *(float4*)(s1w + i * HID + c1) = v1;
        }
    }
    __syncwarp();

    // ---- 30 diffusion steps (warp-private, no __syncthreads) ----
    for (int s = 0; s < NSTEP; s++) {
        const float t = (float)(NSTEP - 1 - s);

        // layer 1: acc = S1 + t*W1[385]; += x @ W1x (K=132 padded); LN+ReLU -> hb
        {
            const float4 wa = *(const float4*)(W1 + (size_t)385 * HID + c0);
            const float4 wb = *(const float4*)(W1 + (size_t)385 * HID + c1);
            #pragma unroll
            for (int i = 0; i < RPW; i++) {
                const float4 sa = *(const float4*)(s1w + i * HID + c0);
                const float4 sb = *(const float4*)(s1w + i * HID + c1);
                acc[i][0] = pk2(fmaf(t, wa.x, sa.x), fmaf(t, wa.y, sa.y));
                acc[i][1] = pk2(fmaf(t, wa.z, sa.z), fmaf(t, wa.w, sa.w));
                acc[i][2] = pk2(fmaf(t, wb.x, sb.x), fmaf(t, wb.y, sb.y));
                acc[i][3] = pk2(fmaf(t, wb.z, sb.z), fmaf(t, wb.w, sb.w));
            }
            gemm2<66>(g_W1xp, xw, XSTR, acc, c0, c1);
            ln_relu_store(acc, hw, g1, be1, c0, c1);
        }
        __syncwarp();

        // layer 2: acc = b2; += h1 @ W2; LN+ReLU -> hb
        {
            const float4 ba = *(const float4*)(b2 + c0);
            const float4 bb = *(const float4*)(b2 + c1);
            #pragma unroll
            for (int i = 0; i < RPW; i++) {
                acc[i][0] = pk2(ba.x, ba.y); acc[i][1] = pk2(ba.z, ba.w);
                acc[i][2] = pk2(bb.x, bb.y); acc[i][3] = pk2(bb.z, bb.w);
            }
            gemm2<128>(W2, hw, HID, acc, c0, c1);
            __syncwarp();                      // WAR: all lanes done reading hb
            ln_relu_store(acc, hw, g2, be2, c0, c1);
        }
        __syncwarp();

        // layer 3: noise = h2 @ W3 + b3; x -= 0.1*noise
        {
            u64 a3[RPW][2];
            const float4 b3v = *(const float4*)(b3 + c0);
            #pragma unroll
            for (int i = 0; i < RPW; i++) {
                a3[i][0] = pk2(b3v.x, b3v.y);
                a3[i][1] = pk2(b3v.z, b3v.w);
            }
            // main 128 cols (4 per lane), ping-pong prefetch
            {
                u64 wA[4], wB[4];
                float2 aA[RPW], aB[RPW];
                loadw32(wA, 0, c0);
                loada2(aA, hw, HID, 0);
                #pragma unroll 1
                for (int jb = 0; jb < 127; jb += 2) {
                    loadw32(wB, jb + 1, c0);
                    loada2(aB, hw, HID, jb + 1);
                    fmab32(wA, aA, a3);
                    if (jb + 2 < 128) {
                        loadw32(wA, jb + 2, c0);
                        loada2(aA, hw, HID, jb + 2);
                    }
                    fmab32(wB, aB, a3);
                }
            }
            // col 128: lane-strided partial dot + butterfly reduce per row
            float a128[RPW];
            #pragma unroll
            for (int i = 0; i < RPW; i++) a128[i] = 0.0f;
            #pragma unroll
            for (int j = 0; j < 8; j++) {
                #pragma unroll
                for (int i = 0; i < RPW; i++) {
                    const float hv = hw[i * HID + lane + 32 * j];
                    a128[i] = fmaf(hv, w128[j], a128[i]);
                }
            }
            #pragma unroll
            for (int i = 0; i < RPW; i++) {
                #pragma unroll
                for (int o = 16; o > 0; o >>= 1)
                    a128[i] += __shfl_xor_sync(0xffffffffu, a128[i], o);
            }
            // x update
            #pragma unroll
            for (int i = 0; i < RPW; i++) {
                float4 xo = *(float4*)(xw + i * XSTR + c0);
                const float2 n0 = up2(a3[i][0]), n1 = up2(a3[i][1]);
                xo.x -= 0.1f * n0.x;
                xo.y -= 0.1f * n0.y;
                xo.z -= 0.1f * n1.x;
                xo.w -= 0.1f * n1.y;
                *(float4*)(xw + i * XSTR + c0) = xo;
                if (lane == 0)
                    xw[i * XSTR + 128] -= 0.1f * (b3L + a128[i]);
            }
        }
        __syncwarp();
    }

    // ---- epilogue: masked gumbel softmax argmax (straight-through) + tanh ----
    #pragma unroll
    for (int i = 0; i < RPW; i++) {
        const size_t gr = grow0 + rbase + i;
        const float4 xv = *(const float4*)(xw + i * XSTR + c0);
        const float4 mk = *(const float4*)(amask  + gr * 128 + c0);
        const float4 gn = *(const float4*)(gumbel + gr * 128 + c0);
        float z[4];
        z[0] = xv.x + (1.0f - mk.x) * (-1e9f) + gn.x;
        z[1] = xv.y + (1.0f - mk.y) * (-1e9f) + gn.y;
        z[2] = xv.z + (1.0f - mk.z) * (-1e9f) + gn.z;
        z[3] = xv.w + (1.0f - mk.w) * (-1e9f) + gn.w;
        float best = z[0]; int bi = c0;
        #pragma unroll
        for (int j = 1; j < 4; j++) if (z[j] > best) { best = z[j]; bi = c0 + j; }
        #pragma unroll
        for (int o = 16; o > 0; o >>= 1) {
            float ov = __shfl_xor_sync(0xffffffffu, best, o);
            int   oi = __shfl_xor_sync(0xffffffffu, bi,   o);
            if (ov > best || (ov == best && oi < bi)) { best = ov; bi = oi; }
        }
        float e[4]; float sl = 0.0f;
        #pragma unroll
        for (int j = 0; j < 4; j++) { e[j] = expf(z[j] - best); sl += e[j]; }
        #pragma unroll
        for (int o = 16; o > 0; o >>= 1) sl += __shfl_xor_sync(0xffffffffu, sl, o);
        #pragma unroll
        for (int j = 0; j < 4; j++) {
            const float p  = e[j] / sl;
            const float yh = (c0 + j == bi) ? 1.0f : 0.0f;
            const float tv = yh + p;
            out[gr * ADIM + c0 + j] = tv - p;
        }
        if (lane == 0) out[gr * ADIM + 128] = tanhf(xw[i * XSTR + 128]);
    }
}

extern "C" void kernel_launch(void* const* d_in, const int* in_sizes, int n_in,
                              void* d_out, int out_size)
{
    const float* state  = (const float*)d_in[0];
    const float* amask  = (const float*)d_in[1];
    const float* x_init = (const float*)d_in[2];
    const float* gumbel = (const float*)d_in[3];
    const float* W1     = (const float*)d_in[4];
    const float* b1     = (const float*)d_in[5];
    const float* g1     = (const float*)d_in[6];
    const float* be1    = (const float*)d_in[7];
    const float* W2     = (const float*)d_in[8];
    const float* b2     = (const float*)d_in[9];
    const float* g2     = (const float*)d_in[10];
    const float* be2    = (const float*)d_in[11];
    const float* W3     = (const float*)d_in[12];
    const float* b3     = (const float*)d_in[13];
    float* out          = (float*)d_out;

    pack_kernel<<<(132 * HID + 255) / 256, 256>>>(W1, W3);

    cudaFuncSetAttribute(actor_kernel,
                         cudaFuncAttributeMaxDynamicSharedMemorySize,
                         (int)SMEM_BYTES);

    actor_kernel<<<NROWS / TM, 128, SMEM_BYTES>>>(
        state, amask, x_init, gumbel,
        W1, b1, g1, be1, W2, b2, g2, be2, b3, out);
}

// round 10
// speedup vs baseline: 1.0124x; 1.0124x over previous
#include <cuda_runtime.h>
#include <cstdint>
#include <math.h>

// ---------------- problem constants ----------------
#define NROWS   65536
#define SDIM    256
#define ADIM    129
#define HID     256
#define NSTEP   30
#define EPS_LN  1e-5f

#define TM      32      // rows per CTA
#define RPW     8       // rows per warp (4 warps * 8 = 32)
#define XSTR    132     // padded float stride for x rows

typedef unsigned long long u64;

// packed fp32x2 helpers (sm_103a FFMA2)
__device__ __forceinline__ u64 pk2(float lo, float hi) {
    u64 r; asm("mov.b64 %0,{%1,%2};" : "=l"(r) : "f"(lo), "f"(hi)); return r;
}
__device__ __forceinline__ float2 up2(u64 v) {
    float lo, hi; asm("mov.b64 {%0,%1},%2;" : "=f"(lo), "=f"(hi) : "l"(v));
    float2 f; f.x = lo; f.y = hi; return f;
}
__device__ __forceinline__ void fma2(u64 &d, u64 a, u64 b) {
    asm("fma.rn.f32x2 %0,%1,%2,%0;" : "+l"(d) : "l"(a), "l"(b));
}

// W1 x-part (rows 256..384) zero-padded to 132 k-rows, stride 256
__device__ float g_W1xp[132 * HID];
// W3 zero-padded to 132 cols, stride 132
__device__ float g_W3p[HID * 132];
// S1 = state @ W1[0:256,:] + b1, spilled to global (64 MB, L2/L1-serviced).
// Written and read by the SAME thread -> no synchronization needed.
__device__ float g_S1[(size_t)NROWS * HID];

__global__ void pack_kernel(const float* __restrict__ W1, const float* __restrict__ W3) {
    int i = blockIdx.x * blockDim.x + threadIdx.x;
    if (i < 132 * HID) {
        int k = i / HID, c = i - k * HID;
        g_W1xp[i] = (k < 129) ? W1[(size_t)(SDIM + k) * HID + c] : 0.0f;
    }
    if (i < HID * 132) {
        int k = i / 132, c = i - k * 132;
        g_W3p[i] = (c < ADIM) ? W3[k * ADIM + c] : 0.0f;
    }
}

// ---- weights: one 4-k block (256-wide row) as u64 halves, accumulator-ready ----
__device__ __forceinline__ void loadw_u64(u64 w[16], const float* __restrict__ Wg,
                                          int jb, int c0, int c1) {
    #pragma unroll
    for (int j = 0; j < 4; j++) {
        const float* p = Wg + (size_t)(jb * 4 + j) * HID;
        const ulonglong2 a = *(const ulonglong2*)(p + c0);
        const ulonglong2 b = *(const ulonglong2*)(p + c1);
        w[4*j+0] = a.x; w[4*j+1] = a.y; w[4*j+2] = b.x; w[4*j+3] = b.y;
    }
}

// ---- activations: one 4-k block for 8 rows (broadcast LDS.128) ----
__device__ __forceinline__ void loadav(float4 av[RPW], const float* __restrict__ src,
                                       int sstr, int jb) {
    #pragma unroll
    for (int i = 0; i < RPW; i++)
        av[i] = *(const float4*)(src + i * sstr + jb * 4);
}

// ---- FMA one 4-k block ----
__device__ __forceinline__ void fmablock(const u64 w[16], const float4 av[RPW],
                                         u64 acc[RPW][4]) {
    #pragma unroll
    for (int j = 0; j < 4; j++) {
        #pragma unroll
        for (int i = 0; i < RPW; i++) {
            const float v = (j == 0) ? av[i].x : (j == 1) ? av[i].y
                          : (j == 2) ? av[i].z : av[i].w;
            const u64 xv = pk2(v, v);
            fma2(acc[i][0], w[4*j+0], xv);
            fma2(acc[i][1], w[4*j+1], xv);
            fma2(acc[i][2], w[4*j+2], xv);
            fma2(acc[i][3], w[4*j+3], xv);
        }
    }
}

// ---- GEMM: single-buffered 4-k blocks (regs fit 3 CTAs/SM; latency hidden
//      by 3 warps/SMSP + L1 hits on the shared weight stream) ----
template<int KB>
__device__ __forceinline__ void gemm_sb(const float* __restrict__ Wg,
                                        const float* __restrict__ src, int sstr,
                                        u64 acc[RPW][4], int c0, int c1)
{
    #pragma unroll 1
    for (int jb = 0; jb < KB; jb++) {
        u64 w[16];
        float4 av[RPW];
        loadw_u64(w, Wg, jb, c0, c1);
        loadav(av, src, sstr, jb);
        fmablock(w, av, acc);
    }
}

// ---- layer-3 variant: 4 cols/lane, weights g_W3p (stride 132) ----
__device__ __forceinline__ void loadw3_u64(u64 w[8], int jb, int c0) {
    #pragma unroll
    for (int j = 0; j < 4; j++) {
        const ulonglong2 a = *(const ulonglong2*)(g_W3p + (size_t)(jb * 4 + j) * 132 + c0);
        w[2*j] = a.x; w[2*j+1] = a.y;
    }
}
__device__ __forceinline__ void fmablock3(const u64 w[8], const float4 av[RPW],
                                          u64 acc[RPW][2]) {
    #pragma unroll
    for (int j = 0; j < 4; j++) {
        #pragma unroll
        for (int i = 0; i < RPW; i++) {
            const float v = (j == 0) ? av[i].x : (j == 1) ? av[i].y
                          : (j == 2) ? av[i].z : av[i].w;
            const u64 xv = pk2(v, v);
            fma2(acc[i][0], w[2*j],   xv);
            fma2(acc[i][1], w[2*j+1], xv);
        }
    }
}

// LayerNorm (two-pass) + ReLU + store to smem (stride 256)
__device__ __forceinline__ void ln_relu_store(u64 acc[RPW][4], float* __restrict__ dst,
                                              const float* __restrict__ g,
                                              const float* __restrict__ be,
                                              int c0, int c1)
{
    const float4 ga = *(const float4*)(g + c0);
    const float4 gb = *(const float4*)(g + c1);
    const float4 ba = *(const float4*)(be + c0);
    const float4 bb = *(const float4*)(be + c1);
    #pragma unroll
    for (int i = 0; i < RPW; i++) {
        float2 a0 = up2(acc[i][0]), a1 = up2(acc[i][1]);
        float2 a2 = up2(acc[i][2]), a3 = up2(acc[i][3]);
        float s = ((a0.x + a0.y) + (a1.x + a1.y)) + ((a2.x + a2.y) + (a3.x + a3.y));
        #pragma unroll
        for (int o = 16; o > 0; o >>= 1) s += __shfl_xor_sync(0xffffffffu, s, o);
        const float m = s * (1.0f / 256.0f);
        const float d0 = a0.x - m, d1 = a0.y - m, d2 = a1.x - m, d3 = a1.y - m;
        const float d4 = a2.x - m, d5 = a2.y - m, d6 = a3.x - m, d7 = a3.y - m;
        float ss = ((d0*d0 + d1*d1) + (d2*d2 + d3*d3)) + ((d4*d4 + d5*d5) + (d6*d6 + d7*d7));
        #pragma unroll
        for (int o = 16; o > 0; o >>= 1) ss += __shfl_xor_sync(0xffffffffu, ss, o);
        const float inv = rsqrtf(ss * (1.0f / 256.0f) + EPS_LN);
        float4 h0, h1;
        h0.x = fmaxf(d0 * inv * ga.x + ba.x, 0.0f);
        h0.y = fmaxf(d1 * inv * ga.y + ba.y, 0.0f);
        h0.z = fmaxf(d2 * inv * ga.z + ba.z, 0.0f);
        h0.w = fmaxf(d3 * inv * ga.w + ba.w, 0.0f);
        h1.x = fmaxf(d4 * inv * gb.x + bb.x, 0.0f);
        h1.y = fmaxf(d5 * inv * gb.y + bb.y, 0.0f);
        h1.z = fmaxf(d6 * inv * gb.z + bb.z, 0.0f);
        h1.w = fmaxf(d7 * inv * gb.w + bb.w, 0.0f);
        *(float4*)(dst + i * HID + c0) = h0;
        *(float4*)(dst + i * HID + c1) = h1;
    }
}

// smem per CTA: h [32][256] + x [32][132] = 49664 B -> 3 CTAs/SM (145.5 KB)
#define HBF   (TM * HID)
#define XSF   (TM * XSTR)
#define SMEM_BYTES ((HBF + XSF) * sizeof(float))

__global__ void __launch_bounds__(128, 3)
actor_kernel(const float* __restrict__ state,  const float* __restrict__ amask,
             const float* __restrict__ x_init, const float* __restrict__ gumbel,
             const float* __restrict__ W1,     const float* __restrict__ b1,
             const float* __restrict__ g1,     const float* __restrict__ be1,
             const float* __restrict__ W2,     const float* __restrict__ b2,
             const float* __restrict__ g2,     const float* __restrict__ be2,
             const float* __restrict__ b3,     float* __restrict__ out)
{
    extern __shared__ float sm[];
    float* hb = sm;                    // [TM][256] h buffer
    float* xs = sm + HBF;              // [TM][132] x (129 live + zero pad)

    const int lane  = threadIdx.x & 31;
    const int wid   = threadIdx.x >> 5;
    const int rbase = wid * RPW;
    const size_t grow0 = (size_t)blockIdx.x * TM;
    const int c0 = lane * 4;
    const int c1 = 128 + lane * 4;

    float* xw  = xs + rbase * XSTR;
    float* hw  = hb + rbase * HID;
    float* s1w = g_S1 + (grow0 + rbase) * HID;   // global, thread-private access

    // ---- load x rows (stride 129, scalar coalesced) + zero pads ----
    #pragma unroll
    for (int i = 0; i < RPW; i++) {
        const size_t gr = grow0 + rbase + i;
        const float* xp = x_init + gr * ADIM;
        #pragma unroll
        for (int j = 0; j < 4; j++) xw[i * XSTR + lane + 32 * j] = xp[lane + 32 * j];
        if (lane == 0) xw[i * XSTR + 128] = xp[128];
        if (lane >= 1 && lane <= 3) xw[i * XSTR + 128 + lane] = 0.0f;
    }
    // ---- stage state rows in hb ----
    #pragma unroll
    for (int i = 0; i < RPW; i++) {
        const float* sp = state + (grow0 + rbase + i) * SDIM;
        *(float4*)(hw + i * HID + c0) = *(const float4*)(sp + c0);
        *(float4*)(hw + i * HID + c1) = *(const float4*)(sp + c1);
    }
    __syncwarp();

    // step-invariant preloads
    float w128[8];  // W3 col 128, lane-strided over k
    #pragma unroll
    for (int j = 0; j < 8; j++) w128[j] = g_W3p[(size_t)(lane + 32 * j) * 132 + 128];
    const float b3L = __ldg(b3 + 128);

    u64 acc[RPW][4];

    // ---- S1 = state @ W1[0:256,:] + b1 (hoisted), spill to g_S1 ----
    {
        const float4 ba = *(const float4*)(b1 + c0);
        const float4 bb = *(const float4*)(b1 + c1);
        #pragma unroll
        for (int i = 0; i < RPW; i++) {
            acc[i][0] = pk2(ba.x, ba.y); acc[i][1] = pk2(ba.z, ba.w);
            acc[i][2] = pk2(bb.x, bb.y); acc[i][3] = pk2(bb.z, bb.w);
        }
        gemm_sb<64>(W1, hw, HID, acc, c0, c1);
        #pragma unroll
        for (int i = 0; i < RPW; i++) {
            float2 a0 = up2(acc[i][0]), a1 = up2(acc[i][1]);
            float2 a2 = up2(acc[i][2]), a3 = up2(acc[i][3]);
            float4 v0; v0.x = a0.x; v0.y = a0.y; v0.z = a1.x; v0.w = a1.y;
            float4 v1; v1.x = a2.x; v1.y = a2.y; v1.z = a3.x; v1.w = a3.y;
            *(float4*)(s1w + i * HID + c0) = v0;
            *(float4*)(s1w + i * HID + c1) = v1;
        }
    }
    __syncwarp();

    // ---- 30 diffusion steps (warp-private, no __syncthreads) ----
    for (int s = 0; s < NSTEP; s++) {
        const float t = (float)(NSTEP - 1 - s);

        // layer 1: acc = S1 + t*W1[385]; += x @ W1x (K=132 padded); LN+ReLU -> hb
        {
            const float4 wa = *(const float4*)(W1 + (size_t)385 * HID + c0);
            const float4 wb = *(const float4*)(W1 + (size_t)385 * HID + c1);
            #pragma unroll
            for (int i = 0; i < RPW; i++) {
                const float4 sa = *(const float4*)(s1w + i * HID + c0);
                const float4 sb = *(const float4*)(s1w + i * HID + c1);
                acc[i][0] = pk2(fmaf(t, wa.x, sa.x), fmaf(t, wa.y, sa.y));
                acc[i][1] = pk2(fmaf(t, wa.z, sa.z), fmaf(t, wa.w, sa.w));
                acc[i][2] = pk2(fmaf(t, wb.x, sb.x), fmaf(t, wb.y, sb.y));
                acc[i][3] = pk2(fmaf(t, wb.z, sb.z), fmaf(t, wb.w, sb.w));
            }
            gemm_sb<33>(g_W1xp, xw, XSTR, acc, c0, c1);
            ln_relu_store(acc, hw, g1, be1, c0, c1);
        }
        __syncwarp();

        // layer 2: acc = b2; += h1 @ W2; LN+ReLU -> hb
        {
            const float4 ba = *(const float4*)(b2 + c0);
            const float4 bb = *(const float4*)(b2 + c1);
            #pragma unroll
            for (int i = 0; i < RPW; i++) {
                acc[i][0] = pk2(ba.x, ba.y); acc[i][1] = pk2(ba.z, ba.w);
                acc[i][2] = pk2(bb.x, bb.y); acc[i][3] = pk2(bb.z, bb.w);
            }
            gemm_sb<64>(W2, hw, HID, acc, c0, c1);
            __syncwarp();                      // WAR: all lanes done reading hb
            ln_relu_store(acc, hw, g2, be2, c0, c1);
        }
        __syncwarp();

        // layer 3: noise = h2 @ W3 + b3; x -= 0.1*noise
        {
            u64 a3[RPW][2];
            const float4 b3v = *(const float4*)(b3 + c0);
            #pragma unroll
            for (int i = 0; i < RPW; i++) {
                a3[i][0] = pk2(b3v.x, b3v.y);
                a3[i][1] = pk2(b3v.z, b3v.w);
            }
            // main 128 cols (4 per lane), single-buffered 4-k blocks
            #pragma unroll 1
            for (int jb = 0; jb < 64; jb++) {
                u64 w[8];
                float4 av[RPW];
                loadw3_u64(w, jb, c0);
                loadav(av, hw, HID, jb);
                fmablock3(w, av, a3);
            }
            // col 128: lane-strided partial dot + butterfly reduce per row
            float a128[RPW];
            #pragma unroll
            for (int i = 0; i < RPW; i++) a128[i] = 0.0f;
            #pragma unroll
            for (int j = 0; j < 8; j++) {
                #pragma unroll
                for (int i = 0; i < RPW; i++) {
                    const float hv = hw[i * HID + lane + 32 * j];
                    a128[i] = fmaf(hv, w128[j], a128[i]);
                }
            }
            #pragma unroll
            for (int i = 0; i < RPW; i++) {
                #pragma unroll
                for (int o = 16; o > 0; o >>= 1)
                    a128[i] += __shfl_xor_sync(0xffffffffu, a128[i], o);
            }
            // x update
            #pragma unroll
            for (int i = 0; i < RPW; i++) {
                float4 xo = *(float4*)(xw + i * XSTR + c0);
                const float2 n0 = up2(a3[i][0]), n1 = up2(a3[i][1]);
                xo.x -= 0.1f * n0.x;
                xo.y -= 0.1f * n0.y;
                xo.z -= 0.1f * n1.x;
                xo.w -= 0.1f * n1.y;
                *(float4*)(xw + i * XSTR + c0) = xo;
                if (lane == 0)
                    xw[i * XSTR + 128] -= 0.1f * (b3L + a128[i]);
            }
        }
        __syncwarp();
    }

    // ---- epilogue: masked gumbel softmax argmax (straight-through) + tanh ----
    #pragma unroll
    for (int i = 0; i < RPW; i++) {
        const size_t gr = grow0 + rbase + i;
        const float4 xv = *(const float4*)(xw + i * XSTR + c0);
        const float4 mk = *(const float4*)(amask  + gr * 128 + c0);
        const float4 gn = *(const float4*)(gumbel + gr * 128 + c0);
        float z[4];
        z[0] = xv.x + (1.0f - mk.x) * (-1e9f) + gn.x;
        z[1] = xv.y + (1.0f - mk.y) * (-1e9f) + gn.y;
        z[2] = xv.z + (1.0f - mk.z) * (-1e9f) + gn.z;
        z[3] = xv.w + (1.0f - mk.w) * (-1e9f) + gn.w;
        float best = z[0]; int bi = c0;
        #pragma unroll
        for (int j = 1; j < 4; j++) if (z[j] > best) { best = z[j]; bi = c0 + j; }
        #pragma unroll
        for (int o = 16; o > 0; o >>= 1) {
            float ov = __shfl_xor_sync(0xffffffffu, best, o);
            int   oi = __shfl_xor_sync(0xffffffffu, bi,   o);
            if (ov > best || (ov == best && oi < bi)) { best = ov; bi = oi; }
        }
        float e[4]; float sl = 0.0f;
        #pragma unroll
        for (int j = 0; j < 4; j++) { e[j] = expf(z[j] - best); sl += e[j]; }
        #pragma unroll
        for (int o = 16; o > 0; o >>= 1) sl += __shfl_xor_sync(0xffffffffu, sl, o);
        #pragma unroll
        for (int j = 0; j < 4; j++) {
            const float p  = e[j] / sl;
            const float yh = (c0 + j == bi) ? 1.0f : 0.0f;
            const float tv = yh + p;
            out[gr * ADIM + c0 + j] = tv - p;
        }
        if (lane == 0) out[gr * ADIM + 128] = tanhf(xw[i * XSTR + 128]);
    }
}

extern "C" void kernel_launch(void* const* d_in, const int* in_sizes, int n_in,
                              void* d_out, int out_size)
{
    const float* state  = (const float*)d_in[0];
    const float* amask  = (const float*)d_in[1];
    const float* x_init = (const float*)d_in[2];
    const float* gumbel = (const float*)d_in[3];
    const float* W1     = (const float*)d_in[4];
    const float* b1     = (const float*)d_in[5];
    const float* g1     = (const float*)d_in[6];
    const float* be1    = (const float*)d_in[7];
    const float* W2     = (const float*)d_in[8];
    const float* b2     = (const float*)d_in[9];
    const float* g2     = (const float*)d_in[10];
    const float* be2    = (const float*)d_in[11];
    const float* W3     = (const float*)d_in[12];
    const float* b3     = (const float*)d_in[13];
    float* out          = (float*)d_out;

    pack_kernel<<<(132 * HID + 255) / 256, 256>>>(W1, W3);

    cudaFuncSetAttribute(actor_kernel,
                         cudaFuncAttributeMaxDynamicSharedMemorySize,
                         (int)SMEM_BYTES);

    actor_kernel<<<NROWS / TM, 128, SMEM_BYTES>>>(
        state, amask, x_init, gumbel,
        W1, b1, g1, be1, W2, b2, g2, be2, b3, out);
}